// round 3
// baseline (speedup 1.0000x reference)
#include <cuda_runtime.h>
#include <math.h>

// ---------------------------------------------------------------------------
// MultilayerGRU: B=32, S=512, I=H=O=1024, L=2
// Per layer: batched x-projection GEMMs (all timesteps), then ONE persistent
// recurrence kernel (software grid barrier, 2 phases/step), finally one
// output-projection GEMM. ~12 graph nodes total (fixes graph-upload-memory
// rule violation seen with 2060 nodes). All fp32.
// ---------------------------------------------------------------------------

#define B_  32
#define S_  512
#define IN_ 1024
#define H_  1024
#define OUT_ 1024
#define L_  2
#define M_  (B_ * S_)      /* 16384 */
#define N3_ (3 * H_)       /* 3072  */

#define HT_PITCH 33
#define SMEM_HT_BYTES (H_ * HT_PITCH * 4)  /* 135168 */
#define NBLK 128           /* persistent-kernel grid; <= 148 SMs, 1 blk/SM */

// ---------------- device scratch (static allocation is allowed) ------------
__device__ float g_xT[(size_t)M_ * IN_];   // x re-laid out to [t*B+b, i]
__device__ float g_gx[(size_t)M_ * N3_];   // x-projections for current layer
__device__ float g_seq[(size_t)M_ * H_];   // layer hidden sequence [t*B+b, h]
__device__ float g_h[B_ * H_];             // current hidden state
__device__ float g_z[B_ * H_];             // z gate for current step
__device__ float g_rh[B_ * H_];            // r * h for current step

// grid barrier state (generation-based; replay-safe)
__device__ unsigned g_bar_count = 0;
__device__ volatile unsigned g_bar_gen = 0;

__device__ __forceinline__ void grid_sync() {
    __syncthreads();
    if (threadIdx.x == 0) {
        __threadfence();
        unsigned gen = g_bar_gen;
        if (atomicAdd(&g_bar_count, 1u) == NBLK - 1u) {
            g_bar_count = 0;
            __threadfence();
            g_bar_gen = gen + 1u;
        } else {
            while (g_bar_gen == gen) __nanosleep(32);
        }
    }
    __syncthreads();
}

// ---------------------------------------------------------------------------
// x[b][t][i] -> g_xT[(t*B+b)][i]
// ---------------------------------------------------------------------------
__global__ void k_transpose_x(const float* __restrict__ x) {
    int row = blockIdx.x;               // t*B + b
    int t = row / B_;
    int b = row % B_;
    const float4* src = (const float4*)(x + ((size_t)b * S_ + t) * IN_);
    float4* dst = (float4*)(g_xT + (size_t)row * IN_);
    for (int i = threadIdx.x; i < IN_ / 4; i += blockDim.x) dst[i] = src[i];
}

// ---------------------------------------------------------------------------
// g_h[b][c] = h0[b][layer][c]
// ---------------------------------------------------------------------------
__global__ void k_load_h(const float* __restrict__ h0, int layer) {
    int idx = blockIdx.x * blockDim.x + threadIdx.x;  // [0, B*H)
    int b = idx / H_;
    int c = idx % H_;
    g_h[idx] = h0[((size_t)b * L_ + layer) * H_ + c];
}

// ---------------------------------------------------------------------------
// Tiled SGEMM:  C[m][n] = sum_k A[m][k] * W[n][k]  + bias[n]
//   A = (asel ? g_seq : g_xT), M=16384, K=1024 fixed.
//   BM=128, BN=64, BK=16, 256 threads, 8x4 register tile.
//   permC=0: C = g_gx, index (m*ldc + col0 + n)
//   permC=1: C = Cout, index ((b*S + t)*ldc + n) with m = t*B + b
// ---------------------------------------------------------------------------
__global__ void __launch_bounds__(256) k_sgemm(
    int asel,
    const float* __restrict__ W,
    const float* __restrict__ bias,
    float* __restrict__ Cout,
    int K, int ldc, int col0, int permC)
{
    const float* __restrict__ A = asel ? g_seq : g_xT;

    __shared__ float As[16][128 + 2];
    __shared__ float Ws[16][64 + 2];

    int m0 = blockIdx.y * 128;
    int n0 = blockIdx.x * 64;
    int tid = threadIdx.x;
    int tx = tid & 15;          // 0..15  -> 4 output columns
    int ty = tid >> 4;          // 0..15  -> 8 output rows

    int lr = tid >> 2;          // 0..63
    int lk = (tid & 3) * 4;     // 0,4,8,12

    const float* Aload0 = A + (size_t)(m0 + lr) * K + lk;
    const float* Aload1 = Aload0 + (size_t)64 * K;
    const float* Wload  = W + (size_t)(n0 + lr) * K + lk;

    float acc[8][4];
#pragma unroll
    for (int i = 0; i < 8; i++)
#pragma unroll
        for (int j = 0; j < 4; j++) acc[i][j] = 0.f;

    for (int k0 = 0; k0 < K; k0 += 16) {
        float4 av0 = *(const float4*)(Aload0 + k0);
        float4 av1 = *(const float4*)(Aload1 + k0);
        float4 wv  = *(const float4*)(Wload + k0);
        __syncthreads();
        As[lk + 0][lr]      = av0.x;
        As[lk + 1][lr]      = av0.y;
        As[lk + 2][lr]      = av0.z;
        As[lk + 3][lr]      = av0.w;
        As[lk + 0][lr + 64] = av1.x;
        As[lk + 1][lr + 64] = av1.y;
        As[lk + 2][lr + 64] = av1.z;
        As[lk + 3][lr + 64] = av1.w;
        Ws[lk + 0][lr] = wv.x;
        Ws[lk + 1][lr] = wv.y;
        Ws[lk + 2][lr] = wv.z;
        Ws[lk + 3][lr] = wv.w;
        __syncthreads();
#pragma unroll
        for (int k = 0; k < 16; k++) {
            float a[8], w[4];
#pragma unroll
            for (int i = 0; i < 8; i++) a[i] = As[k][ty * 8 + i];
#pragma unroll
            for (int j = 0; j < 4; j++) w[j] = Ws[k][tx * 4 + j];
#pragma unroll
            for (int i = 0; i < 8; i++)
#pragma unroll
                for (int j = 0; j < 4; j++) acc[i][j] += a[i] * w[j];
        }
    }

#pragma unroll
    for (int i = 0; i < 8; i++) {
        int m = m0 + ty * 8 + i;
#pragma unroll
        for (int j = 0; j < 4; j++) {
            int n = n0 + tx * 4 + j;
            float v = acc[i][j] + (bias ? bias[n] : 0.f);
            if (permC) {
                int b = m & (B_ - 1);
                int t = m >> 5;
                Cout[((size_t)b * S_ + t) * ldc + n] = v;
            } else {
                g_gx[(size_t)m * ldc + col0 + n] = v;
            }
        }
    }
}

// ---------------------------------------------------------------------------
// Load src[B][H] into smem transposed: s_hT[k*33 + b] = src[b][k]
// LDG coalesced over k, STS conflict-free (stride 33).
// ---------------------------------------------------------------------------
__device__ __forceinline__ void load_hT(const float* __restrict__ src, float* s_hT) {
    for (int idx = threadIdx.x; idx < B_ * (H_ / 4); idx += blockDim.x) {
        int b  = idx >> 8;      // H/4 = 256 per batch row
        int kq = idx & 255;
#pragma unroll
        for (int j = 0; j < 4; j++) {
            int k = kq + j * 256;
            s_hT[k * HT_PITCH + b] = src[b * H_ + k];
        }
    }
}

// ---------------------------------------------------------------------------
// Skinny GEMM cores: warp owns 1-2 weight columns; lane owns a k-stripe and
// all 32 batch rows. Butterfly all-reduce over lanes at the end; after the
// reduce, lane b holds the value for batch row b.
// ---------------------------------------------------------------------------
__device__ __forceinline__ void skinny_dot2(
    const float* __restrict__ W0, const float* __restrict__ W1,
    const float* __restrict__ s_hT, int lane, float& outA, float& outB)
{
    float accA[32], accB[32];
#pragma unroll
    for (int b = 0; b < 32; b++) { accA[b] = 0.f; accB[b] = 0.f; }

    for (int k0 = 0; k0 < H_; k0 += 32) {
        float w0 = W0[k0 + lane];
        float w1 = W1[k0 + lane];
        const float* hp = s_hT + (k0 + lane) * HT_PITCH;
#pragma unroll
        for (int b = 0; b < 32; b++) {
            float hv = hp[b];
            accA[b] += hv * w0;
            accB[b] += hv * w1;
        }
    }
#pragma unroll
    for (int off = 16; off > 0; off >>= 1) {
#pragma unroll
        for (int b = 0; b < 32; b++) {
            accA[b] += __shfl_xor_sync(0xffffffffu, accA[b], off);
            accB[b] += __shfl_xor_sync(0xffffffffu, accB[b], off);
        }
    }
    float v0 = 0.f, v1 = 0.f;
#pragma unroll
    for (int b = 0; b < 32; b++)
        if (lane == b) { v0 = accA[b]; v1 = accB[b]; }
    outA = v0;
    outB = v1;
}

__device__ __forceinline__ void skinny_dot1(
    const float* __restrict__ W0,
    const float* __restrict__ s_hT, int lane, float& outA)
{
    float accA[32];
#pragma unroll
    for (int b = 0; b < 32; b++) accA[b] = 0.f;

    for (int k0 = 0; k0 < H_; k0 += 32) {
        float w0 = W0[k0 + lane];
        const float* hp = s_hT + (k0 + lane) * HT_PITCH;
#pragma unroll
        for (int b = 0; b < 32; b++) accA[b] += hp[b] * w0;
    }
#pragma unroll
    for (int off = 16; off > 0; off >>= 1) {
#pragma unroll
        for (int b = 0; b < 32; b++)
            accA[b] += __shfl_xor_sync(0xffffffffu, accA[b], off);
    }
    float v0 = 0.f;
#pragma unroll
    for (int b = 0; b < 32; b++)
        if (lane == b) v0 = accA[b];
    outA = v0;
}

__device__ __forceinline__ float sigmoidf_(float x) {
    return 1.f / (1.f + expf(-x));
}

// ---------------------------------------------------------------------------
// Persistent recurrence kernel: ONE launch per layer covers all S_ steps.
// Grid = NBLK(128) blocks x 256 threads, 135KB dyn smem -> 1 block/SM, all
// blocks resident (128 <= 148 SMs) so the software grid barrier is safe.
//
// Per step:
//   phase 1: block handles 16 of 2048 (gate,column) pairs; z gate for blocks
//            [0,64), r gate for blocks [64,128). Writes g_z, g_rh.
//   grid_sync
//   phase 2: block handles 8 of 1024 columns (1 col/warp): g = tanh(...),
//            h' = h + z*(g-h). Writes g_h, g_seq (+ final hidden at t=S-1).
//   grid_sync
// ---------------------------------------------------------------------------
__global__ void __launch_bounds__(256) k_gru_recur(
    const float* __restrict__ Wzh, const float* __restrict__ Wrh,
    const float* __restrict__ Wgh, int layer, float* __restrict__ hid_out)
{
    extern __shared__ float s_hT[];
    int warp = threadIdx.x >> 5;
    int lane = threadIdx.x & 31;

    // phase-1 column assignment
    int vc = blockIdx.x * 16 + warp * 2;   // [0, 2048)
    int gate = vc >> 10;                   // 0=z, 1=r
    int c1 = vc & 1023;
    const float* Wb = gate ? Wrh : Wzh;
    const float* W0 = Wb + ((size_t)layer * H_ + c1) * H_;
    const float* W1 = W0 + H_;

    // phase-2 column assignment (1 column per warp)
    int c2 = blockIdx.x * 8 + warp;        // [0, 1024)
    const float* Wg0 = Wgh + ((size_t)layer * H_ + c2) * H_;

    for (int t = 0; t < S_; t++) {
        // ---- phase 1: z and r ----
        load_hT(g_h, s_hT);
        __syncthreads();

        float v0, v1;
        skinny_dot2(W0, W1, s_hT, lane, v0, v1);

        size_t row = (size_t)t * B_ + lane;   // b = lane
        if (gate == 0) {
            g_z[lane * H_ + c1]     = sigmoidf_(v0 + g_gx[row * N3_ + c1]);
            g_z[lane * H_ + c1 + 1] = sigmoidf_(v1 + g_gx[row * N3_ + c1 + 1]);
        } else {
            float r0 = sigmoidf_(v0 + g_gx[row * N3_ + H_ + c1]);
            float r1 = sigmoidf_(v1 + g_gx[row * N3_ + H_ + c1 + 1]);
            g_rh[lane * H_ + c1]     = r0 * g_h[lane * H_ + c1];
            g_rh[lane * H_ + c1 + 1] = r1 * g_h[lane * H_ + c1 + 1];
        }

        grid_sync();

        // ---- phase 2: g and h update ----
        load_hT(g_rh, s_hT);
        __syncthreads();

        float vg;
        skinny_dot1(Wg0, s_hT, lane, vg);

        float gv = tanhf(vg + g_gx[row * N3_ + 2 * H_ + c2]);
        float hv = g_h[lane * H_ + c2];
        float zv = g_z[lane * H_ + c2];
        float hn = hv + zv * (gv - hv);

        g_h[lane * H_ + c2] = hn;
        g_seq[row * H_ + c2] = hn;
        if (hid_out && t == S_ - 1)
            hid_out[((size_t)lane * L_ + layer) * H_ + c2] = hn;

        grid_sync();
    }
}

// ---------------------------------------------------------------------------
// Launch
// ---------------------------------------------------------------------------
extern "C" void kernel_launch(void* const* d_in, const int* in_sizes, int n_in,
                              void* d_out, int out_size) {
    (void)in_sizes; (void)n_in;
    const float* x   = (const float*)d_in[0];
    const float* h0  = (const float*)d_in[1];
    const float* Wzx = (const float*)d_in[2];
    const float* bz  = (const float*)d_in[3];
    const float* Wzh = (const float*)d_in[4];
    const float* Wrx = (const float*)d_in[5];
    const float* br  = (const float*)d_in[6];
    const float* Wrh = (const float*)d_in[7];
    const float* Wgx = (const float*)d_in[8];
    const float* bg  = (const float*)d_in[9];
    const float* Wgh = (const float*)d_in[10];
    const float* Wo  = (const float*)d_in[11];
    const float* bo  = (const float*)d_in[12];

    float* out = (float*)d_out;
    float* y_out = out;                                  // [B,S,O]
    const long long need = (long long)B_ * S_ * OUT_ + (long long)B_ * L_ * H_;
    float* hid_out = ((long long)out_size >= need) ? out + (size_t)B_ * S_ * OUT_
                                                   : nullptr;

    cudaFuncSetAttribute(k_gru_recur,
        cudaFuncAttributeMaxDynamicSharedMemorySize, SMEM_HT_BYTES);

    // 1) x -> [t*B+b, i]
    k_transpose_x<<<M_, 256>>>(x);

    dim3 ggrid(OUT_ / 64, M_ / 128);  // (16, 128)

    for (int layer = 0; layer < L_; layer++) {
        // load initial hidden for this layer
        k_load_h<<<(B_ * H_) / 256, 256>>>(h0, layer);

        int asel = (layer == 0) ? 0 : 1;
        const size_t wxo = (size_t)layer * H_ * IN_;
        // batched x-projections (+bias) into g_gx columns [0,1024),[1024,2048),[2048,3072)
        k_sgemm<<<ggrid, 256>>>(asel, Wzx + wxo, bz + (size_t)layer * H_,
                                nullptr, IN_, N3_, 0, 0);
        k_sgemm<<<ggrid, 256>>>(asel, Wrx + wxo, br + (size_t)layer * H_,
                                nullptr, IN_, N3_, H_, 0);
        k_sgemm<<<ggrid, 256>>>(asel, Wgx + wxo, bg + (size_t)layer * H_,
                                nullptr, IN_, N3_, 2 * H_, 0);

        // full-sequence recurrence in ONE persistent launch
        k_gru_recur<<<NBLK, 256, SMEM_HT_BYTES>>>(Wzh, Wrh, Wgh, layer, hid_out);
    }

    // output projection: y[b][t][:] = seq[t*B+b][:] @ Wo^T + bo
    k_sgemm<<<ggrid, 256>>>(1, Wo, bo, y_out, H_, OUT_, 0, 1);
}

// round 4
// speedup vs baseline: 1.5564x; 1.5564x over previous
#include <cuda_runtime.h>
#include <math.h>

// ---------------------------------------------------------------------------
// MultilayerGRU: B=32, S=512, I=H=O=1024, L=2
// Per layer: batched x-projection GEMMs (all timesteps), then ONE persistent
// recurrence kernel (software grid barrier, 2 phases/step), finally one
// output-projection GEMM.
// R4: recurrence rework — weights register/smem-cached across all 512 steps,
// [b][k] float4 tile, 31-shuffle multi-reduce, balanced phase 2.
// ---------------------------------------------------------------------------

#define B_  32
#define S_  512
#define IN_ 1024
#define H_  1024
#define OUT_ 1024
#define L_  2
#define M_  (B_ * S_)      /* 16384 */
#define N3_ (3 * H_)       /* 3072  */

#define PITCH 1024                          /* words; [b][k] tile */
#define TILE_WORDS (B_ * PITCH)             /* 32768 */
#define WG_WORDS   (8 * H_)                 /* 8192: 8 phase-2 weight cols */
#define SMEM_BYTES ((TILE_WORDS + WG_WORDS) * 4)  /* 163840 */
#define NBLK 128            /* persistent grid; <=148 SMs, 1 blk/SM */

// ---------------- device scratch (static allocation is allowed) ------------
__device__ float g_xT[(size_t)M_ * IN_];   // x re-laid out to [t*B+b, i]
__device__ float g_gx[(size_t)M_ * N3_];   // x-projections for current layer
__device__ float g_seq[(size_t)M_ * H_];   // layer hidden sequence [t*B+b, h]
__device__ float g_h[B_ * H_];             // current hidden state
__device__ float g_z[B_ * H_];             // z gate for current step
__device__ float g_rh[B_ * H_];            // r * h for current step

// grid barrier state (generation-based; replay-safe)
__device__ unsigned g_bar_count = 0;
__device__ volatile unsigned g_bar_gen = 0;

__device__ __forceinline__ void grid_sync() {
    __syncthreads();
    if (threadIdx.x == 0) {
        __threadfence();
        unsigned gen = g_bar_gen;
        if (atomicAdd(&g_bar_count, 1u) == NBLK - 1u) {
            g_bar_count = 0;
            __threadfence();
            g_bar_gen = gen + 1u;
        } else {
            while (g_bar_gen == gen) __nanosleep(32);
        }
        __threadfence();
    }
    __syncthreads();
}

// ---------------------------------------------------------------------------
// x[b][t][i] -> g_xT[(t*B+b)][i]
// ---------------------------------------------------------------------------
__global__ void k_transpose_x(const float* __restrict__ x) {
    int row = blockIdx.x;               // t*B + b
    int t = row / B_;
    int b = row % B_;
    const float4* src = (const float4*)(x + ((size_t)b * S_ + t) * IN_);
    float4* dst = (float4*)(g_xT + (size_t)row * IN_);
    for (int i = threadIdx.x; i < IN_ / 4; i += blockDim.x) dst[i] = src[i];
}

// ---------------------------------------------------------------------------
// g_h[b][c] = h0[b][layer][c]
// ---------------------------------------------------------------------------
__global__ void k_load_h(const float* __restrict__ h0, int layer) {
    int idx = blockIdx.x * blockDim.x + threadIdx.x;  // [0, B*H)
    int b = idx / H_;
    int c = idx % H_;
    g_h[idx] = h0[((size_t)b * L_ + layer) * H_ + c];
}

// ---------------------------------------------------------------------------
// Tiled SGEMM:  C[m][n] = sum_k A[m][k] * W[n][k]  + bias[n]   (unchanged)
// ---------------------------------------------------------------------------
__global__ void __launch_bounds__(256) k_sgemm(
    int asel,
    const float* __restrict__ W,
    const float* __restrict__ bias,
    float* __restrict__ Cout,
    int K, int ldc, int col0, int permC)
{
    const float* __restrict__ A = asel ? g_seq : g_xT;

    __shared__ float As[16][128 + 2];
    __shared__ float Ws[16][64 + 2];

    int m0 = blockIdx.y * 128;
    int n0 = blockIdx.x * 64;
    int tid = threadIdx.x;
    int tx = tid & 15;
    int ty = tid >> 4;

    int lr = tid >> 2;
    int lk = (tid & 3) * 4;

    const float* Aload0 = A + (size_t)(m0 + lr) * K + lk;
    const float* Aload1 = Aload0 + (size_t)64 * K;
    const float* Wload  = W + (size_t)(n0 + lr) * K + lk;

    float acc[8][4];
#pragma unroll
    for (int i = 0; i < 8; i++)
#pragma unroll
        for (int j = 0; j < 4; j++) acc[i][j] = 0.f;

    for (int k0 = 0; k0 < K; k0 += 16) {
        float4 av0 = *(const float4*)(Aload0 + k0);
        float4 av1 = *(const float4*)(Aload1 + k0);
        float4 wv  = *(const float4*)(Wload + k0);
        __syncthreads();
        As[lk + 0][lr]      = av0.x;
        As[lk + 1][lr]      = av0.y;
        As[lk + 2][lr]      = av0.z;
        As[lk + 3][lr]      = av0.w;
        As[lk + 0][lr + 64] = av1.x;
        As[lk + 1][lr + 64] = av1.y;
        As[lk + 2][lr + 64] = av1.z;
        As[lk + 3][lr + 64] = av1.w;
        Ws[lk + 0][lr] = wv.x;
        Ws[lk + 1][lr] = wv.y;
        Ws[lk + 2][lr] = wv.z;
        Ws[lk + 3][lr] = wv.w;
        __syncthreads();
#pragma unroll
        for (int k = 0; k < 16; k++) {
            float a[8], w[4];
#pragma unroll
            for (int i = 0; i < 8; i++) a[i] = As[k][ty * 8 + i];
#pragma unroll
            for (int j = 0; j < 4; j++) w[j] = Ws[k][tx * 4 + j];
#pragma unroll
            for (int i = 0; i < 8; i++)
#pragma unroll
                for (int j = 0; j < 4; j++) acc[i][j] += a[i] * w[j];
        }
    }

#pragma unroll
    for (int i = 0; i < 8; i++) {
        int m = m0 + ty * 8 + i;
#pragma unroll
        for (int j = 0; j < 4; j++) {
            int n = n0 + tx * 4 + j;
            float v = acc[i][j] + (bias ? bias[n] : 0.f);
            if (permC) {
                int b = m & (B_ - 1);
                int t = m >> 5;
                Cout[((size_t)b * S_ + t) * ldc + n] = v;
            } else {
                g_gx[(size_t)m * ldc + col0 + n] = v;
            }
        }
    }
}

// ---------------------------------------------------------------------------
// Load src[B][H] (gmem, via L2) into smem tile s_h[b][k], pitch 1024 words.
// Warp w loads 512B-contiguous kq-block w of every batch row b; STS.128
// conflict-free, LDG.128 coalesced. 32 LDG.128 per warp.
// ---------------------------------------------------------------------------
__device__ __forceinline__ void load_tile(const float* __restrict__ src,
                                          float* __restrict__ s_h) {
    const int warp = threadIdx.x >> 5;
    const int lane = threadIdx.x & 31;
#pragma unroll
    for (int io = 0; io < 4; io++) {
        float4 v[8];
#pragma unroll
        for (int iu = 0; iu < 8; iu++) {
            int b = io * 8 + iu;
            int kq = warp * 32 + lane;           // float4 index within row
            v[iu] = __ldcg(reinterpret_cast<const float4*>(src + (size_t)b * H_) + kq);
        }
#pragma unroll
        for (int iu = 0; iu < 8; iu++) {
            int b = io * 8 + iu;
            int kq = warp * 32 + lane;
            reinterpret_cast<float4*>(s_h + (size_t)b * PITCH)[kq] = v[iu];
        }
    }
}

// ---------------------------------------------------------------------------
// Multi-reduce: 32 per-lane partial arrays -> lane l returns total of array l.
// 31 shuffles (16+8+4+2+1), all register indices constant.
// ---------------------------------------------------------------------------
__device__ __forceinline__ float warp_multireduce(float* a, int lane) {
#pragma unroll
    for (int off = 16; off >= 1; off >>= 1) {
#pragma unroll
        for (int b = 0; b < off; b++) {
            bool hi = (lane & off) != 0;
            float send = hi ? a[b] : a[b + off];
            float recv = __shfl_xor_sync(0xffffffffu, send, off);
            a[b] = (hi ? a[b + off] : a[b]) + recv;
        }
    }
    return a[0];
}

__device__ __forceinline__ float sigmoidf_(float x) {
    return 1.f / (1.f + expf(-x));
}

// ---------------------------------------------------------------------------
// Persistent recurrence kernel. NBLK(128) blocks x 256 thr, 160KB dyn smem
// -> 1 block/SM, all resident, software grid barrier safe.
//
// Phase 1: 8 warps x 2 cols of (z|r) [2048 cols total]; weights in REGISTERS
//          (loaded once). Writes g_z, g_rh.
// Phase 2: warps 0-3 x 2 cols of g [1024 cols]; weights in SMEM (loaded
//          once). h' = h + z*(g-h); writes g_h, g_seq (+ final hidden).
// ---------------------------------------------------------------------------
__global__ void __launch_bounds__(256, 1) k_gru_recur(
    const float* __restrict__ Wzh, const float* __restrict__ Wrh,
    const float* __restrict__ Wgh, int layer, float* __restrict__ hid_out)
{
    extern __shared__ float smem[];
    float* s_h  = smem;                    // [32][1024]
    float* s_wg = smem + TILE_WORDS;       // [8][1024]

    const int warp = threadIdx.x >> 5;
    const int lane = threadIdx.x & 31;

    // ---- phase-1 static assignment: 2 cols per warp over z(1024)+r(1024)
    const int vc   = blockIdx.x * 16 + warp * 2;
    const int gate = vc >> 10;             // 0=z, 1=r
    const int c1   = vc & 1023;
    const float* Wb = gate ? Wrh : Wzh;
    const float* W0 = Wb + ((size_t)layer * H_ + c1) * H_;
    const float* W1 = W0 + H_;

    float4 w0r[8], w1r[8];                 // weight stripes, live whole kernel
#pragma unroll
    for (int kc = 0; kc < 8; kc++) {
        w0r[kc] = reinterpret_cast<const float4*>(W0 + kc * 128)[lane];
        w1r[kc] = reinterpret_cast<const float4*>(W1 + kc * 128)[lane];
    }

    // ---- phase-2 static assignment: warps 0..3, 2 cols each
    const int c2 = blockIdx.x * 8 + warp * 2;    // valid when warp < 4

    // phase-2 weights -> smem once (8 cols x 1024)
    for (int cc = 0; cc < 8; cc++) {
        const float4* src = reinterpret_cast<const float4*>(
            Wgh + ((size_t)layer * H_ + blockIdx.x * 8 + cc) * H_);
        reinterpret_cast<float4*>(s_wg + cc * H_)[threadIdx.x] = src[threadIdx.x];
    }
    __syncthreads();

    for (int t = 0; t < S_; t++) {
        const size_t row = (size_t)t * B_ + lane;     // b = lane

        // ================= phase 1: z and r =================
        load_tile(g_h, s_h);
        float gx0 = __ldcg(&g_gx[row * N3_ + (gate ? H_ : 0) + c1]);
        float gx1 = __ldcg(&g_gx[row * N3_ + (gate ? H_ : 0) + c1 + 1]);
        __syncthreads();

        float accA[32], accB[32];
#pragma unroll
        for (int b = 0; b < 32; b++) { accA[b] = 0.f; accB[b] = 0.f; }
#pragma unroll
        for (int kc = 0; kc < 8; kc++) {
            const float4* hp = reinterpret_cast<const float4*>(s_h + kc * 128) + lane;
            float4 w0 = w0r[kc], w1 = w1r[kc];
#pragma unroll
            for (int b = 0; b < 32; b++) {
                float4 h4 = hp[b * 256];
                accA[b] = fmaf(h4.x, w0.x, accA[b]);
                accA[b] = fmaf(h4.y, w0.y, accA[b]);
                accA[b] = fmaf(h4.z, w0.z, accA[b]);
                accA[b] = fmaf(h4.w, w0.w, accA[b]);
                accB[b] = fmaf(h4.x, w1.x, accB[b]);
                accB[b] = fmaf(h4.y, w1.y, accB[b]);
                accB[b] = fmaf(h4.z, w1.z, accB[b]);
                accB[b] = fmaf(h4.w, w1.w, accB[b]);
            }
        }
        float v0 = warp_multireduce(accA, lane);
        float v1 = warp_multireduce(accB, lane);

        if (gate == 0) {
            g_z[lane * H_ + c1]     = sigmoidf_(v0 + gx0);
            g_z[lane * H_ + c1 + 1] = sigmoidf_(v1 + gx1);
        } else {
            float h0v = s_h[lane * PITCH + c1];        // own h from tile
            float h1v = s_h[lane * PITCH + c1 + 1];
            g_rh[lane * H_ + c1]     = sigmoidf_(v0 + gx0) * h0v;
            g_rh[lane * H_ + c1 + 1] = sigmoidf_(v1 + gx1) * h1v;
        }

        grid_sync();

        // ================= phase 2: g and h update =================
        load_tile(g_rh, s_h);
        float gxg0 = 0.f, gxg1 = 0.f, hv0 = 0.f, hv1 = 0.f, zv0 = 0.f, zv1 = 0.f;
        if (warp < 4) {
            gxg0 = __ldcg(&g_gx[row * N3_ + 2 * H_ + c2]);
            gxg1 = __ldcg(&g_gx[row * N3_ + 2 * H_ + c2 + 1]);
            hv0  = __ldcg(&g_h[lane * H_ + c2]);
            hv1  = __ldcg(&g_h[lane * H_ + c2 + 1]);
            zv0  = __ldcg(&g_z[lane * H_ + c2]);
            zv1  = __ldcg(&g_z[lane * H_ + c2 + 1]);
        }
        __syncthreads();

        if (warp < 4) {
            float acc0[32], acc1[32];
#pragma unroll
            for (int b = 0; b < 32; b++) { acc0[b] = 0.f; acc1[b] = 0.f; }
#pragma unroll
            for (int kc = 0; kc < 8; kc++) {
                const float4* hp = reinterpret_cast<const float4*>(s_h + kc * 128) + lane;
                float4 wA = reinterpret_cast<const float4*>(s_wg + (warp * 2) * H_ + kc * 128)[lane];
                float4 wB = reinterpret_cast<const float4*>(s_wg + (warp * 2 + 1) * H_ + kc * 128)[lane];
#pragma unroll
                for (int b = 0; b < 32; b++) {
                    float4 h4 = hp[b * 256];
                    acc0[b] = fmaf(h4.x, wA.x, acc0[b]);
                    acc0[b] = fmaf(h4.y, wA.y, acc0[b]);
                    acc0[b] = fmaf(h4.z, wA.z, acc0[b]);
                    acc0[b] = fmaf(h4.w, wA.w, acc0[b]);
                    acc1[b] = fmaf(h4.x, wB.x, acc1[b]);
                    acc1[b] = fmaf(h4.y, wB.y, acc1[b]);
                    acc1[b] = fmaf(h4.z, wB.z, acc1[b]);
                    acc1[b] = fmaf(h4.w, wB.w, acc1[b]);
                }
            }
            float vg0 = warp_multireduce(acc0, lane);
            float vg1 = warp_multireduce(acc1, lane);

            float gv0 = tanhf(vg0 + gxg0);
            float gv1 = tanhf(vg1 + gxg1);
            float hn0 = fmaf(zv0, gv0 - hv0, hv0);
            float hn1 = fmaf(zv1, gv1 - hv1, hv1);

            g_h[lane * H_ + c2]     = hn0;
            g_h[lane * H_ + c2 + 1] = hn1;
            g_seq[row * H_ + c2]     = hn0;
            g_seq[row * H_ + c2 + 1] = hn1;
            if (hid_out && t == S_ - 1) {
                hid_out[((size_t)lane * L_ + layer) * H_ + c2]     = hn0;
                hid_out[((size_t)lane * L_ + layer) * H_ + c2 + 1] = hn1;
            }
        }

        grid_sync();
    }
}

// ---------------------------------------------------------------------------
// Launch
// ---------------------------------------------------------------------------
extern "C" void kernel_launch(void* const* d_in, const int* in_sizes, int n_in,
                              void* d_out, int out_size) {
    (void)in_sizes; (void)n_in;
    const float* x   = (const float*)d_in[0];
    const float* h0  = (const float*)d_in[1];
    const float* Wzx = (const float*)d_in[2];
    const float* bz  = (const float*)d_in[3];
    const float* Wzh = (const float*)d_in[4];
    const float* Wrx = (const float*)d_in[5];
    const float* br  = (const float*)d_in[6];
    const float* Wrh = (const float*)d_in[7];
    const float* Wgx = (const float*)d_in[8];
    const float* bg  = (const float*)d_in[9];
    const float* Wgh = (const float*)d_in[10];
    const float* Wo  = (const float*)d_in[11];
    const float* bo  = (const float*)d_in[12];

    float* out = (float*)d_out;
    float* y_out = out;                                  // [B,S,O]
    const long long need = (long long)B_ * S_ * OUT_ + (long long)B_ * L_ * H_;
    float* hid_out = ((long long)out_size >= need) ? out + (size_t)B_ * S_ * OUT_
                                                   : nullptr;

    cudaFuncSetAttribute(k_gru_recur,
        cudaFuncAttributeMaxDynamicSharedMemorySize, SMEM_BYTES);

    // 1) x -> [t*B+b, i]
    k_transpose_x<<<M_, 256>>>(x);

    dim3 ggrid(OUT_ / 64, M_ / 128);  // (16, 128)

    for (int layer = 0; layer < L_; layer++) {
        k_load_h<<<(B_ * H_) / 256, 256>>>(h0, layer);

        int asel = (layer == 0) ? 0 : 1;
        const size_t wxo = (size_t)layer * H_ * IN_;
        k_sgemm<<<ggrid, 256>>>(asel, Wzx + wxo, bz + (size_t)layer * H_,
                                nullptr, IN_, N3_, 0, 0);
        k_sgemm<<<ggrid, 256>>>(asel, Wrx + wxo, br + (size_t)layer * H_,
                                nullptr, IN_, N3_, H_, 0);
        k_sgemm<<<ggrid, 256>>>(asel, Wgx + wxo, bg + (size_t)layer * H_,
                                nullptr, IN_, N3_, 2 * H_, 0);

        // full-sequence recurrence in ONE persistent launch
        k_gru_recur<<<NBLK, 256, SMEM_BYTES>>>(Wzh, Wrh, Wgh, layer, hid_out);
    }

    // output projection: y[b][t][:] = seq[t*B+b][:] @ Wo^T + bo
    k_sgemm<<<ggrid, 256>>>(1, Wo, bo, y_out, H_, OUT_, 0, 1);
}